// round 4
// baseline (speedup 1.0000x reference)
#include <cuda_runtime.h>

#define K 19
#define L 2048
#define B 512
#define START_ID 17
#define PAD_ID 18
#define NEG -1000.0f
#define BPST 20
#define NW 4            // rows (warps) per block
#define NSEG 16         // backtrack segments per row
#define CPL 10          // boundary chains per lane: ceil(16*19/32)
#define FULL 0xffffffffu

// 1 if mask elements are 4 bytes (int32/float32), 0 if 1 byte (bool/uint8)
__device__ int g_elt4;

__global__ void detect_kernel(const unsigned char* __restrict__ m) {
    __shared__ int found;
    if (threadIdx.x == 0) found = 0;
    __syncthreads();
    int f = 0;
    for (int i = threadIdx.x * 4 + 1; i < 65536; i += blockDim.x * 4)
        f |= m[i];
    if (f) found = 1;
    __syncthreads();
    if (threadIdx.x == 0) g_elt4 = found ? 0 : 1;
}

__global__ void __launch_bounds__(NW * 32, 1) viterbi_kernel(
    const float* __restrict__ P,          // [B, L, K]
    const float* __restrict__ Tm,         // [K, K]: T[j*K+k], prev k -> cur j
    const unsigned char* __restrict__ mask,
    float* __restrict__ out)              // [B, L] float32
{
    extern __shared__ unsigned char dsm[];            // NW * L * BPST bytes
    __shared__ unsigned char fmap[NW][NSEG][K];
    __shared__ unsigned char eseg[NW][NSEG];

    const int wid  = threadIdx.x >> 5;
    const int lane = threadIdx.x & 31;
    const int b    = blockIdx.x * NW + wid;           // this warp's row
    const int j    = (lane < K) ? lane : 0;

    unsigned char* __restrict__ bp = dsm + wid * (L * BPST);

    // ---- sequence length for this row ----
    int len = 0;
    if (g_elt4) {
        const unsigned int* m = (const unsigned int*)mask + (size_t)b * L;
        for (int i = lane; i < L; i += 32) len += (m[i] != 0u);
    } else {
        const unsigned char* m = mask + (size_t)b * L;
        for (int i = lane; i < L; i += 32) len += (m[i] != 0);
    }
#pragma unroll
    for (int o = 16; o; o >>= 1) len += __shfl_xor_sync(FULL, len, o);

    // ---- per-lane transition row + PAD entry ----
    float Trow[K];
#pragma unroll
    for (int k = 0; k < K; ++k) Trow[k] = Tm[j * K + k];
    const float Tpad = Tm[PAD_ID * K + j];

    const float* Pb = P + (size_t)b * L * K;

    // emission prefetch pipeline, depth 4
    float ebuf[4];
#pragma unroll
    for (int i = 0; i < 4; ++i) {
        int tt = (i < len) ? i : (len - 1);
        ebuf[i] = __ldg(Pb + tt * K + j);
    }

    // ---- forward pass (lane j owns output state j; DP via shuffles) ----
    float nd = (j == START_ID && lane < K) ? 0.0f : NEG;
    unsigned bpoff = 0;

    for (int t = 0; t < len; ++t) {
        const float emit = ebuf[t & 3];
        {
            int tp = t + 4;
            if (tp >= len) tp = len - 1;
            ebuf[t & 3] = __ldg(Pb + tp * K + j);
        }

        float v[K];
        int ix[K];
#pragma unroll
        for (int k = 0; k < K; ++k) {
            v[k] = __shfl_sync(FULL, nd, k) + Trow[k];
            ix[k] = k;
        }

        // balanced max tree carrying argmax; left wins ties (= first occurrence,
        // since left subtree indices are always smaller). fmaxf(l,r)==l when l>=r.
#pragma unroll
        for (int w = 1; w < K; w *= 2)
#pragma unroll
            for (int i = 0; i + w < K; i += 2 * w) {
                const bool p = v[i] >= v[i + w];
                ix[i] = p ? ix[i] : ix[i + w];
                v[i] = fmaxf(v[i], v[i + w]);
            }

        if (lane < K) bp[bpoff + lane] = (unsigned char)ix[0];
        bpoff += BPST;

        nd = v[0] + emit;
    }

    // ---- final transition into PAD, first-occurrence argmax (lane 0) ----
    const float fv = (lane < K) ? (nd + Tpad) : NEG;
    int last = 0;
    {
        float bestf = __shfl_sync(FULL, fv, 0);
#pragma unroll
        for (int k = 1; k < K; ++k) {
            const float vk = __shfl_sync(FULL, fv, k);
            if (vk > bestf) { bestf = vk; last = k; }   // > keeps first max
        }
    }

    float* ob = out + (size_t)b * L;

    // pad tail with -1.0f
    for (int t = len + lane; t < L; t += 32) ob[t] = -1.0f;

    // ---- backtrack, warp-local two-pass ----
    const int segw = (len + NSEG - 1) / NSEG;           // >= 1
    const int nseg = (len + segw - 1) / segw;           // <= NSEG

    // pass 1: chain (segment i, end-state e) -> state at segment start.
    // 10 chains per lane run interleaved for MLP.
    int cur[CPL], ptr[CPL], stop[CPL];
#pragma unroll
    for (int q = 0; q < CPL; ++q) {
        const int cid = lane + 32 * q;
        if (cid < nseg * K) {
            const int i = cid / K, e = cid - i * K;
            const int t0 = i * segw;
            const int t1 = min(t0 + segw, len);
            cur[q] = e;
            ptr[q] = (t1 - 1) * BPST;
            stop[q] = t0 * BPST;
        } else {
            cur[q] = 0; ptr[q] = 0; stop[q] = 0;
        }
    }
    for (int p = 0; p < segw - 1; ++p) {
#pragma unroll
        for (int q = 0; q < CPL; ++q)
            if (ptr[q] > stop[q]) {
                cur[q] = bp[ptr[q] + cur[q]];
                ptr[q] -= BPST;
            }
    }
#pragma unroll
    for (int q = 0; q < CPL; ++q) {
        const int cid = lane + 32 * q;
        if (cid < nseg * K) {
            const int i = cid / K, e = cid - i * K;
            fmap[wid][i][e] = (unsigned char)cur[q];
        }
    }
    __syncwarp();

    // resolve segment end states top-down (lane 0, <= 16 dependent lookups)
    if (lane == 0) {
        int e = last;
        eseg[wid][nseg - 1] = (unsigned char)e;
        for (int i = nseg - 1; i > 0; --i) {
            const int t0 = i * segw;
            const int pc = fmap[wid][i][e];       // path[t0]
            e = bp[t0 * BPST + pc];               // path[t0-1]
            eseg[wid][i - 1] = (unsigned char)e;
        }
    }
    __syncwarp();

    // pass 2: each lane decodes one segment
    if (lane < nseg) {
        const int t0 = lane * segw;
        const int t1 = min(t0 + segw, len);
        int c = eseg[wid][lane];
        ob[t1 - 1] = (float)c;
        for (int t = t1 - 2; t >= t0; --t) {
            c = bp[(t + 1) * BPST + c];
            ob[t] = (float)c;
        }
    }
}

extern "C" void kernel_launch(void* const* d_in, const int* in_sizes, int n_in,
                              void* d_out, int out_size) {
    const float* P = (const float*)d_in[0];
    const float* T = (const float*)d_in[1];
    const unsigned char* mask = (const unsigned char*)d_in[2];
    float* out = (float*)d_out;

    const int smem = NW * L * BPST;  // 163840 B
    cudaFuncSetAttribute(viterbi_kernel,
                         cudaFuncAttributeMaxDynamicSharedMemorySize, smem);

    detect_kernel<<<1, 256>>>(mask);
    viterbi_kernel<<<B / NW, NW * 32, smem>>>(P, T, mask, out);
}

// round 5
// speedup vs baseline: 1.3247x; 1.3247x over previous
#include <cuda_runtime.h>

#define K 19
#define L 2048
#define B 512
#define START_ID 17
#define PAD_ID 18
#define NEG -1000.0f
#define BPST 20
#define NW 4            // rows (warps) per block
#define NSEG 16         // backtrack segments per row
#define CPL 10          // boundary chains per lane: ceil(16*19/32)
#define FULL 0xffffffffu

// 1 if mask elements are 4 bytes (int32/float32), 0 if 1 byte (bool/uint8)
__device__ int g_elt4;

__global__ void detect_kernel(const unsigned char* __restrict__ m) {
    __shared__ int found;
    if (threadIdx.x == 0) found = 0;
    __syncthreads();
    int f = 0;
    for (int i = threadIdx.x * 4 + 1; i < 65536; i += blockDim.x * 4)
        f |= m[i];
    if (f) found = 1;
    __syncthreads();
    if (threadIdx.x == 0) g_elt4 = found ? 0 : 1;
}

__global__ void __launch_bounds__(NW * 32, 1) viterbi_kernel(
    const float* __restrict__ P,          // [B, L, K]
    const float* __restrict__ Tm,         // [K, K]: T[j*K+k], prev k -> cur j
    const unsigned char* __restrict__ mask,
    float* __restrict__ out)              // [B, L] float32
{
    extern __shared__ unsigned char dsm[];            // NW * L * BPST bytes
    __shared__ unsigned char fmap[NW][NSEG][K];
    __shared__ unsigned char eseg[NW][NSEG];

    const int wid  = threadIdx.x >> 5;
    const int lane = threadIdx.x & 31;
    const int b    = blockIdx.x * NW + wid;           // this warp's row
    const int j    = (lane < K) ? lane : 0;

    unsigned char* __restrict__ bp = dsm + wid * (L * BPST);

    // ---- sequence length for this row ----
    int len = 0;
    if (g_elt4) {
        const unsigned int* m = (const unsigned int*)mask + (size_t)b * L;
        for (int i = lane; i < L; i += 32) len += (m[i] != 0u);
    } else {
        const unsigned char* m = mask + (size_t)b * L;
        for (int i = lane; i < L; i += 32) len += (m[i] != 0);
    }
#pragma unroll
    for (int o = 16; o; o >>= 1) len += __shfl_xor_sync(FULL, len, o);

    // ---- per-lane transition row ----
    float Trow[K];
#pragma unroll
    for (int k = 0; k < K; ++k) Trow[k] = Tm[j * K + k];

    const float* Pb = P + (size_t)b * L * K;

    // emission prefetch pipeline, depth 4
    float ebuf[4];
#pragma unroll
    for (int i = 0; i < 4; ++i) {
        int tt = (i < len) ? i : (len - 1);
        ebuf[i] = __ldg(Pb + tt * K + j);
    }

    // ---- forward pass (lane j owns output state j; DP via shuffles) ----
    float nd = (j == START_ID && lane < K) ? 0.0f : NEG;
    unsigned bpoff = 0;

    for (int t = 0; t < len; ++t) {
        const float emit = ebuf[t & 3];
        {
            int tp = t + 4;
            if (tp >= len) tp = len - 1;
            ebuf[t & 3] = __ldg(Pb + tp * K + j);
        }

        // s[k] = DP[k] + T[j,k]  (preserved for argmax mask)
        float s[K];
#pragma unroll
        for (int k = 0; k < K; ++k)
            s[k] = __shfl_sync(FULL, nd, k) + Trow[k];

        // tournament max tree with transient temps; s stays intact.
        // max is exactly associative -> any tree order is bit-exact.
        float a0 = fmaxf(s[0],  s[1]);
        float a1 = fmaxf(s[2],  s[3]);
        float a2 = fmaxf(s[4],  s[5]);
        float a3 = fmaxf(s[6],  s[7]);
        float a4 = fmaxf(s[8],  s[9]);
        float a5 = fmaxf(s[10], s[11]);
        float a6 = fmaxf(s[12], s[13]);
        float a7 = fmaxf(s[14], s[15]);
        float a8 = fmaxf(s[16], s[17]);
        a0 = fmaxf(a0, a1);
        a2 = fmaxf(a2, a3);
        a4 = fmaxf(a4, a5);
        a6 = fmaxf(a6, a7);
        a8 = fmaxf(a8, s[18]);
        a0 = fmaxf(a0, a2);
        a4 = fmaxf(a4, a6);
        a0 = fmaxf(a0, a4);
        const float best = fmaxf(a0, a8);

        // first-occurrence argmax (equality mask, off critical path)
        unsigned mb = 0u;
#pragma unroll
        for (int k = 0; k < K; ++k) mb |= (s[k] == best) ? (1u << k) : 0u;
        if (lane < K) bp[bpoff + lane] = (unsigned char)(__ffs(mb) - 1);
        bpoff += BPST;

        nd = best + emit;
    }

    // ---- final transition into PAD, first-occurrence argmax ----
    const float fv = (lane < K) ? (nd + Tm[PAD_ID * K + j]) : NEG;
    int last = 0;
    {
        float bestf = __shfl_sync(FULL, fv, 0);
#pragma unroll
        for (int k = 1; k < K; ++k) {
            const float vk = __shfl_sync(FULL, fv, k);
            if (vk > bestf) { bestf = vk; last = k; }   // > keeps first max
        }
    }

    float* ob = out + (size_t)b * L;

    // pad tail with -1.0f
    for (int t = len + lane; t < L; t += 32) ob[t] = -1.0f;

    // ---- backtrack, warp-local two-pass ----
    const int segw = (len + NSEG - 1) / NSEG;           // >= 1
    const int nseg = (len + segw - 1) / segw;           // <= NSEG

    // pass 1: chain (segment i, end-state e) -> state at segment start.
    int cur[CPL], ptr[CPL], stop[CPL];
#pragma unroll
    for (int q = 0; q < CPL; ++q) {
        const int cid = lane + 32 * q;
        if (cid < nseg * K) {
            const int i = cid / K, e = cid - i * K;
            const int t0 = i * segw;
            const int t1 = min(t0 + segw, len);
            cur[q] = e;
            ptr[q] = (t1 - 1) * BPST;
            stop[q] = t0 * BPST;
        } else {
            cur[q] = 0; ptr[q] = 0; stop[q] = 0;
        }
    }
    for (int p = 0; p < segw - 1; ++p) {
#pragma unroll
        for (int q = 0; q < CPL; ++q)
            if (ptr[q] > stop[q]) {
                cur[q] = bp[ptr[q] + cur[q]];
                ptr[q] -= BPST;
            }
    }
#pragma unroll
    for (int q = 0; q < CPL; ++q) {
        const int cid = lane + 32 * q;
        if (cid < nseg * K) {
            const int i = cid / K, e = cid - i * K;
            fmap[wid][i][e] = (unsigned char)cur[q];
        }
    }
    __syncwarp();

    // resolve segment end states top-down (lane 0, <= 16 dependent lookups)
    if (lane == 0) {
        int e = last;
        eseg[wid][nseg - 1] = (unsigned char)e;
        for (int i = nseg - 1; i > 0; --i) {
            const int t0 = i * segw;
            const int pc = fmap[wid][i][e];       // path[t0]
            e = bp[t0 * BPST + pc];               // path[t0-1]
            eseg[wid][i - 1] = (unsigned char)e;
        }
    }
    __syncwarp();

    // pass 2: each lane decodes one segment
    if (lane < nseg) {
        const int t0 = lane * segw;
        const int t1 = min(t0 + segw, len);
        int c = eseg[wid][lane];
        ob[t1 - 1] = (float)c;
        for (int t = t1 - 2; t >= t0; --t) {
            c = bp[(t + 1) * BPST + c];
            ob[t] = (float)c;
        }
    }
}

extern "C" void kernel_launch(void* const* d_in, const int* in_sizes, int n_in,
                              void* d_out, int out_size) {
    const float* P = (const float*)d_in[0];
    const float* T = (const float*)d_in[1];
    const unsigned char* mask = (const unsigned char*)d_in[2];
    float* out = (float*)d_out;

    const int smem = NW * L * BPST;  // 163840 B
    cudaFuncSetAttribute(viterbi_kernel,
                         cudaFuncAttributeMaxDynamicSharedMemorySize, smem);

    detect_kernel<<<1, 256>>>(mask);
    viterbi_kernel<<<B / NW, NW * 32, smem>>>(P, T, mask, out);
}

// round 6
// speedup vs baseline: 1.5616x; 1.1789x over previous
#include <cuda_runtime.h>

#define K 19
#define L 2048
#define B 512
#define START_ID 17
#define PAD_ID 18
#define NEG -1000.0f
#define BPST 20
#define NW 4            // rows (warps) per block
#define NSEG 16         // backtrack segments per row
#define CPL 10          // boundary chains per lane: ceil(16*19/32)
#define FULL 0xffffffffu

// 1 if mask elements are 4 bytes (int32/float32), 0 if 1 byte (bool/uint8)
__device__ int g_elt4;

__global__ void detect_kernel(const unsigned char* __restrict__ m) {
    __shared__ int found;
    if (threadIdx.x == 0) found = 0;
    __syncthreads();
    int f = 0;
    for (int i = threadIdx.x * 4 + 1; i < 65536; i += blockDim.x * 4)
        f |= m[i];
    if (f) found = 1;
    __syncthreads();
    if (threadIdx.x == 0) g_elt4 = found ? 0 : 1;
}

// running (max, argmax) step: strict '>' keeps FIRST occurrence on ties.
// value via fmaxf (exact, associative). One SHFL result live at a time.
#define VSTEP(kk, bb, aa)                                        \
    {                                                            \
        float sk = __shfl_sync(FULL, nd, kk) + Trow[kk];         \
        if (sk > bb) aa = kk;                                    \
        bb = fmaxf(bb, sk);                                      \
    }

__global__ void __launch_bounds__(NW * 32, 1) viterbi_kernel(
    const float* __restrict__ P,          // [B, L, K]
    const float* __restrict__ Tm,         // [K, K]: T[j*K+k], prev k -> cur j
    const unsigned char* __restrict__ mask,
    float* __restrict__ out)              // [B, L] float32
{
    extern __shared__ unsigned char dsm[];            // NW * L * BPST bytes
    __shared__ unsigned char fmap[NW][NSEG][K];
    __shared__ unsigned char eseg[NW][NSEG];

    const int wid  = threadIdx.x >> 5;
    const int lane = threadIdx.x & 31;
    const int b    = blockIdx.x * NW + wid;           // this warp's row
    const int j    = (lane < K) ? lane : 0;

    unsigned char* __restrict__ bp = dsm + wid * (L * BPST);

    // ---- sequence length for this row ----
    int len = 0;
    if (g_elt4) {
        const unsigned int* m = (const unsigned int*)mask + (size_t)b * L;
        for (int i = lane; i < L; i += 32) len += (m[i] != 0u);
    } else {
        const unsigned char* m = mask + (size_t)b * L;
        for (int i = lane; i < L; i += 32) len += (m[i] != 0);
    }
#pragma unroll
    for (int o = 16; o; o >>= 1) len += __shfl_xor_sync(FULL, len, o);

    // ---- per-lane transition row ----
    float Trow[K];
#pragma unroll
    for (int k = 0; k < K; ++k) Trow[k] = Tm[j * K + k];

    const float* Pb = P + (size_t)b * L * K;

    // emission prefetch pipeline, depth 8
    float ebuf[8];
#pragma unroll
    for (int i = 0; i < 8; ++i) {
        int tt = (i < len) ? i : (len - 1);
        ebuf[i] = __ldg(Pb + tt * K + j);
    }

    // ---- forward pass (lane j owns output state j; DP via shuffles) ----
    float nd = (j == START_ID && lane < K) ? 0.0f : NEG;
    unsigned bpoff = 0;

    for (int t = 0; t < len; ++t) {
        const float emit = ebuf[t & 7];
        {
            int tp = t + 8;
            if (tp >= len) tp = len - 1;
            ebuf[t & 7] = __ldg(Pb + tp * K + j);
        }

        // 4 independent running (max,argmax) chains over ordered index ranges
        float b0 = __shfl_sync(FULL, nd, 0)  + Trow[0];  int a0 = 0;
        float b1 = __shfl_sync(FULL, nd, 5)  + Trow[5];  int a1 = 5;
        float b2 = __shfl_sync(FULL, nd, 10) + Trow[10]; int a2 = 10;
        float b3 = __shfl_sync(FULL, nd, 15) + Trow[15]; int a3 = 15;

        VSTEP(1, b0, a0)  VSTEP(2, b0, a0)  VSTEP(3, b0, a0)  VSTEP(4, b0, a0)
        VSTEP(6, b1, a1)  VSTEP(7, b1, a1)  VSTEP(8, b1, a1)  VSTEP(9, b1, a1)
        VSTEP(11, b2, a2) VSTEP(12, b2, a2) VSTEP(13, b2, a2) VSTEP(14, b2, a2)
        VSTEP(16, b3, a3) VSTEP(17, b3, a3) VSTEP(18, b3, a3)

        // merge: strict '>' prefers lower-index chain on ties (first occurrence,
        // since chain index ranges are ordered). fmaxf is exact either way.
        int a01 = (b1 > b0) ? a1 : a0;  float b01 = fmaxf(b0, b1);
        int a23 = (b3 > b2) ? a3 : a2;  float b23 = fmaxf(b2, b3);
        int arg = (b23 > b01) ? a23 : a01;
        const float best = fmaxf(b01, b23);

        if (lane < K) bp[bpoff + lane] = (unsigned char)arg;
        bpoff += BPST;

        nd = best + emit;
    }

    // ---- final transition into PAD, first-occurrence argmax ----
    const float fv = (lane < K) ? (nd + Tm[PAD_ID * K + j]) : NEG;
    int last = 0;
    {
        float bestf = __shfl_sync(FULL, fv, 0);
#pragma unroll
        for (int k = 1; k < K; ++k) {
            const float vk = __shfl_sync(FULL, fv, k);
            if (vk > bestf) { bestf = vk; last = k; }   // > keeps first max
        }
    }

    float* ob = out + (size_t)b * L;

    // pad tail with -1.0f
    for (int t = len + lane; t < L; t += 32) ob[t] = -1.0f;

    // ---- backtrack, warp-local two-pass ----
    const int segw = (len + NSEG - 1) / NSEG;           // >= 1
    const int nseg = (len + segw - 1) / segw;           // <= NSEG

    // pass 1: chain (segment i, end-state e) -> state at segment start.
    int cur[CPL], ptr[CPL], stop[CPL];
#pragma unroll
    for (int q = 0; q < CPL; ++q) {
        const int cid = lane + 32 * q;
        if (cid < nseg * K) {
            const int i = cid / K, e = cid - i * K;
            const int t0 = i * segw;
            const int t1 = min(t0 + segw, len);
            cur[q] = e;
            ptr[q] = (t1 - 1) * BPST;
            stop[q] = t0 * BPST;
        } else {
            cur[q] = 0; ptr[q] = 0; stop[q] = 0;
        }
    }
    for (int p = 0; p < segw - 1; ++p) {
#pragma unroll
        for (int q = 0; q < CPL; ++q)
            if (ptr[q] > stop[q]) {
                cur[q] = bp[ptr[q] + cur[q]];
                ptr[q] -= BPST;
            }
    }
#pragma unroll
    for (int q = 0; q < CPL; ++q) {
        const int cid = lane + 32 * q;
        if (cid < nseg * K) {
            const int i = cid / K, e = cid - i * K;
            fmap[wid][i][e] = (unsigned char)cur[q];
        }
    }
    __syncwarp();

    // resolve segment end states top-down (lane 0, <= 16 dependent lookups)
    if (lane == 0) {
        int e = last;
        eseg[wid][nseg - 1] = (unsigned char)e;
        for (int i = nseg - 1; i > 0; --i) {
            const int t0 = i * segw;
            const int pc = fmap[wid][i][e];       // path[t0]
            e = bp[t0 * BPST + pc];               // path[t0-1]
            eseg[wid][i - 1] = (unsigned char)e;
        }
    }
    __syncwarp();

    // pass 2: each lane decodes one segment
    if (lane < nseg) {
        const int t0 = lane * segw;
        const int t1 = min(t0 + segw, len);
        int c = eseg[wid][lane];
        ob[t1 - 1] = (float)c;
        for (int t = t1 - 2; t >= t0; --t) {
            c = bp[(t + 1) * BPST + c];
            ob[t] = (float)c;
        }
    }
}

extern "C" void kernel_launch(void* const* d_in, const int* in_sizes, int n_in,
                              void* d_out, int out_size) {
    const float* P = (const float*)d_in[0];
    const float* T = (const float*)d_in[1];
    const unsigned char* mask = (const unsigned char*)d_in[2];
    float* out = (float*)d_out;

    const int smem = NW * L * BPST;  // 163840 B
    cudaFuncSetAttribute(viterbi_kernel,
                         cudaFuncAttributeMaxDynamicSharedMemorySize, smem);

    detect_kernel<<<1, 256>>>(mask);
    viterbi_kernel<<<B / NW, NW * 32, smem>>>(P, T, mask, out);
}

// round 7
// speedup vs baseline: 3.3343x; 2.1352x over previous
#include <cuda_runtime.h>

#define K 19
#define L 2048
#define B 512
#define START_ID 17
#define PAD_ID 18
#define NEG -1000.0f
#define NW 4            // rows (warps) per block
#define NSEG 16         // backtrack segments per row
#define CPL 10          // boundary chains per lane: ceil(16*19/32)
#define FULL 0xffffffffu
#define ROWBYTES (L / 4 * 80)   // packed bp: [L/4 groups][20 lanes][4 bytes]

__device__ int g_elt4;

__global__ void detect_kernel(const unsigned char* __restrict__ m) {
    __shared__ int found;
    if (threadIdx.x == 0) found = 0;
    __syncthreads();
    int f = 0;
    for (int i = threadIdx.x * 4 + 1; i < 65536; i += blockDim.x * 4)
        f |= m[i];
    if (f) found = 1;
    __syncthreads();
    if (threadIdx.x == 0) g_elt4 = found ? 0 : 1;
}

// bp(t, c) for packed layout
__device__ __forceinline__ int BPGET(const unsigned char* bp, int t, int c) {
    return bp[((t >> 2) * 80) + (c << 2) + (t & 3)];
}

// chain micro-step: strict '>' keeps FIRST occurrence; SEL-form (no branches)
#define VS(kk, cc, ii)                                            \
    sk = __shfl_sync(FULL, nd, kk) + Trow[kk];                    \
    ii = (sk > cc) ? kk : ii;                                     \
    cc = fmaxf(cc, sk);

// one Viterbi step: consumes EMIT, writes backpointer arg to ARGOUT, updates nd
#define FSTEP(EMIT, ARGOUT) do {                                          \
    float sk;                                                             \
    float c0 = __shfl_sync(FULL, nd, 0)  + Trow[0];  int i0 = 0;          \
    float c1 = __shfl_sync(FULL, nd, 5)  + Trow[5];  int i1 = 5;          \
    float c2 = __shfl_sync(FULL, nd, 10) + Trow[10]; int i2 = 10;         \
    float c3 = __shfl_sync(FULL, nd, 15) + Trow[15]; int i3 = 15;         \
    VS(1, c0, i0)  VS(2, c0, i0)  VS(3, c0, i0)  VS(4, c0, i0)            \
    VS(6, c1, i1)  VS(7, c1, i1)  VS(8, c1, i1)  VS(9, c1, i1)            \
    VS(11, c2, i2) VS(12, c2, i2) VS(13, c2, i2) VS(14, c2, i2)           \
    VS(16, c3, i3) VS(17, c3, i3) VS(18, c3, i3)                          \
    int   i01 = (c1 > c0) ? i1 : i0;  float m01 = fmaxf(c0, c1);          \
    int   i23 = (c3 > c2) ? i3 : i2;  float m23 = fmaxf(c2, c3);          \
    ARGOUT = (m23 > m01) ? i23 : i01;                                     \
    nd = fmaxf(m01, m23) + (EMIT);                                        \
} while (0)

__global__ void __launch_bounds__(NW * 32, 1) viterbi_kernel(
    const float* __restrict__ P,          // [B, L, K]
    const float* __restrict__ Tm,         // [K, K]: T[j*K+k], prev k -> cur j
    const unsigned char* __restrict__ mask,
    float* __restrict__ out)              // [B, L] float32
{
    extern __shared__ unsigned char dsm[];            // NW * ROWBYTES
    __shared__ unsigned char fmap[NW][NSEG][K];
    __shared__ unsigned char eseg[NW][NSEG];

    const int wid  = threadIdx.x >> 5;
    const int lane = threadIdx.x & 31;
    const int b    = blockIdx.x * NW + wid;
    const int j    = (lane < K) ? lane : 0;

    unsigned char* __restrict__ bp = dsm + wid * ROWBYTES;

    // ---- sequence length ----
    int len = 0;
    if (g_elt4) {
        const unsigned int* m = (const unsigned int*)mask + (size_t)b * L;
        for (int i = lane; i < L; i += 32) len += (m[i] != 0u);
    } else {
        const unsigned char* m = mask + (size_t)b * L;
        for (int i = lane; i < L; i += 32) len += (m[i] != 0);
    }
#pragma unroll
    for (int o = 16; o; o >>= 1) len += __shfl_xor_sync(FULL, len, o);

    float Trow[K];
#pragma unroll
    for (int k = 0; k < K; ++k) Trow[k] = Tm[j * K + k];

    const float* Pb = P + (size_t)b * L * K;
    const int lm1 = len - 1;

    // named-register emission pipeline, depth 4
    float e0 = __ldg(Pb + 0 * K + j);
    float e1 = __ldg(Pb + min(1, lm1) * K + j);
    float e2 = __ldg(Pb + min(2, lm1) * K + j);
    float e3 = __ldg(Pb + min(3, lm1) * K + j);

    float nd = (j == START_ID && lane < K) ? 0.0f : NEG;
    unsigned int* bpw = (unsigned int*)bp + lane;     // + 20 per 4-step group

    int t = 0;
    // ---- main loop, 4 steps per iteration ----
    for (; t + 4 <= len; t += 4) {
        int a0, a1, a2, a3;
        FSTEP(e0, a0);  e0 = __ldg(Pb + min(t + 4, lm1) * K + j);
        FSTEP(e1, a1);  e1 = __ldg(Pb + min(t + 5, lm1) * K + j);
        FSTEP(e2, a2);  e2 = __ldg(Pb + min(t + 6, lm1) * K + j);
        FSTEP(e3, a3);  e3 = __ldg(Pb + min(t + 7, lm1) * K + j);
        if (lane < K)
            *bpw = (unsigned)a0 | ((unsigned)a1 << 8) |
                   ((unsigned)a2 << 16) | ((unsigned)a3 << 24);
        bpw += 20;
    }
    // ---- tail (0..3 steps) ----
    {
        const int r = len - t;
        if (r > 0) {
            int a0 = 0, a1 = 0, a2 = 0;
            FSTEP(e0, a0);
            if (r > 1) FSTEP(e1, a1);
            if (r > 2) FSTEP(e2, a2);
            if (lane < K)
                *bpw = (unsigned)a0 | ((unsigned)a1 << 8) | ((unsigned)a2 << 16);
        }
    }

    // ---- final transition into PAD, first-occurrence argmax ----
    const float fv = (lane < K) ? (nd + Tm[PAD_ID * K + j]) : NEG;
    int last = 0;
    {
        float bestf = __shfl_sync(FULL, fv, 0);
#pragma unroll
        for (int k = 1; k < K; ++k) {
            const float vk = __shfl_sync(FULL, fv, k);
            if (vk > bestf) { bestf = vk; last = k; }
        }
    }

    float* ob = out + (size_t)b * L;
    for (int tt = len + lane; tt < L; tt += 32) ob[tt] = -1.0f;

    // ---- backtrack, warp-local two-pass ----
    const int segw = (len + NSEG - 1) / NSEG;
    const int nseg = (len + segw - 1) / segw;

    // pass 1: chain (segment i, end-state e) -> state at segment start
    int cur[CPL], tq[CPL], t0q[CPL];
#pragma unroll
    for (int q = 0; q < CPL; ++q) {
        const int cid = lane + 32 * q;
        if (cid < nseg * K) {
            const int i = cid / K, e = cid - i * K;
            const int t0 = i * segw;
            const int t1 = min(t0 + segw, len);
            cur[q] = e; tq[q] = t1 - 1; t0q[q] = t0;
        } else { cur[q] = 0; tq[q] = 0; t0q[q] = 0; }
    }
    for (int p = 0; p < segw - 1; ++p) {
#pragma unroll
        for (int q = 0; q < CPL; ++q)
            if (tq[q] > t0q[q]) {
                cur[q] = BPGET(bp, tq[q], cur[q]);
                tq[q]--;
            }
    }
#pragma unroll
    for (int q = 0; q < CPL; ++q) {
        const int cid = lane + 32 * q;
        if (cid < nseg * K) {
            const int i = cid / K, e = cid - i * K;
            fmap[wid][i][e] = (unsigned char)cur[q];
        }
    }
    __syncwarp();

    if (lane == 0) {
        int e = last;
        eseg[wid][nseg - 1] = (unsigned char)e;
        for (int i = nseg - 1; i > 0; --i) {
            const int t0 = i * segw;
            const int pc = fmap[wid][i][e];       // path[t0]
            e = BPGET(bp, t0, pc);                // path[t0-1]
            eseg[wid][i - 1] = (unsigned char)e;
        }
    }
    __syncwarp();

    // pass 2: each lane decodes one segment
    if (lane < nseg) {
        const int t0 = lane * segw;
        const int t1 = min(t0 + segw, len);
        int c = eseg[wid][lane];
        ob[t1 - 1] = (float)c;
        for (int tt = t1 - 2; tt >= t0; --tt) {
            c = BPGET(bp, tt + 1, c);
            ob[tt] = (float)c;
        }
    }
}

extern "C" void kernel_launch(void* const* d_in, const int* in_sizes, int n_in,
                              void* d_out, int out_size) {
    const float* P = (const float*)d_in[0];
    const float* T = (const float*)d_in[1];
    const unsigned char* mask = (const unsigned char*)d_in[2];
    float* out = (float*)d_out;

    const int smem = NW * ROWBYTES;  // 163840 B
    cudaFuncSetAttribute(viterbi_kernel,
                         cudaFuncAttributeMaxDynamicSharedMemorySize, smem);

    detect_kernel<<<1, 256>>>(mask);
    viterbi_kernel<<<B / NW, NW * 32, smem>>>(P, T, mask, out);
}

// round 8
// speedup vs baseline: 3.7365x; 1.1206x over previous
#include <cuda_runtime.h>

#define K 19
#define L 2048
#define B 512
#define START_ID 17
#define PAD_ID 18
#define NEG -1000.0f
#define NW 4            // rows (warps) per block
#define NSEG 16         // backtrack segments per row
#define CPL 10          // boundary chains per lane: ceil(16*19/32)
#define FULL 0xffffffffu
#define ROWBYTES (L / 4 * 80)   // packed bp: [L/4 groups][20 lanes][4 bytes]

__device__ int g_elt4;

__global__ void detect_kernel(const unsigned char* __restrict__ m) {
    __shared__ int found;
    if (threadIdx.x == 0) found = 0;
    __syncthreads();
    int f = 0;
    for (int i = threadIdx.x * 4 + 1; i < 65536; i += blockDim.x * 4)
        f |= m[i];
    if (f) found = 1;
    __syncthreads();
    if (threadIdx.x == 0) g_elt4 = found ? 0 : 1;
}

// bp(t, c) for packed layout
__device__ __forceinline__ int BPGET(const unsigned char* bp, int t, int c) {
    return bp[((t >> 2) * 80) + (c << 2) + (t & 3)];
}

// chain micro-step on register copy d[]: strict '>' keeps FIRST occurrence
#define VS(kk, cc, ii)                                            \
    sk = d[kk] + Trow[kk];                                        \
    ii = (sk > cc) ? kk : ii;                                     \
    cc = fmaxf(cc, sk);

// one Viterbi step: DP exchange through SMEM double buffer.
// Reads dpbuf[wid][CUR], writes dpbuf[wid][NXT], one syncwarp.
#define FSTEP(CUR, NXT, EMIT, ARGOUT) do {                                \
    float d[20];                                                          \
    *(float4*)&d[0]  = *(const float4*)&dpbuf[wid][CUR][0];               \
    *(float4*)&d[4]  = *(const float4*)&dpbuf[wid][CUR][4];               \
    *(float4*)&d[8]  = *(const float4*)&dpbuf[wid][CUR][8];               \
    *(float4*)&d[12] = *(const float4*)&dpbuf[wid][CUR][12];              \
    *(float4*)&d[16] = *(const float4*)&dpbuf[wid][CUR][16];              \
    float sk;                                                             \
    float c0 = d[0]  + Trow[0];  int i0 = 0;                              \
    float c1 = d[5]  + Trow[5];  int i1 = 5;                              \
    float c2 = d[10] + Trow[10]; int i2 = 10;                             \
    float c3 = d[15] + Trow[15]; int i3 = 15;                             \
    VS(1, c0, i0)  VS(2, c0, i0)  VS(3, c0, i0)  VS(4, c0, i0)            \
    VS(6, c1, i1)  VS(7, c1, i1)  VS(8, c1, i1)  VS(9, c1, i1)            \
    VS(11, c2, i2) VS(12, c2, i2) VS(13, c2, i2) VS(14, c2, i2)           \
    VS(16, c3, i3) VS(17, c3, i3) VS(18, c3, i3)                          \
    int   i01 = (c1 > c0) ? i1 : i0;  float m01 = fmaxf(c0, c1);          \
    int   i23 = (c3 > c2) ? i3 : i2;  float m23 = fmaxf(c2, c3);          \
    ARGOUT = (m23 > m01) ? i23 : i01;                                     \
    nd = fmaxf(m01, m23) + (EMIT);                                        \
    if (lane < K) dpbuf[wid][NXT][lane] = nd;                             \
    __syncwarp();                                                         \
} while (0)

__global__ void __launch_bounds__(NW * 32, 1) viterbi_kernel(
    const float* __restrict__ P,          // [B, L, K]
    const float* __restrict__ Tm,         // [K, K]: T[j*K+k], prev k -> cur j
    const unsigned char* __restrict__ mask,
    float* __restrict__ out)              // [B, L] float32
{
    extern __shared__ unsigned char dsm[];            // NW * ROWBYTES
    __shared__ __align__(16) float dpbuf[NW][2][20];  // DP double buffer
    __shared__ unsigned char fmap[NW][NSEG][K];
    __shared__ unsigned char eseg[NW][NSEG];

    const int wid  = threadIdx.x >> 5;
    const int lane = threadIdx.x & 31;
    const int b    = blockIdx.x * NW + wid;
    const int j    = (lane < K) ? lane : 0;

    unsigned char* __restrict__ bp = dsm + wid * ROWBYTES;

    // ---- sequence length ----
    int len = 0;
    if (g_elt4) {
        const unsigned int* m = (const unsigned int*)mask + (size_t)b * L;
        for (int i = lane; i < L; i += 32) len += (m[i] != 0u);
    } else {
        const unsigned char* m = mask + (size_t)b * L;
        for (int i = lane; i < L; i += 32) len += (m[i] != 0);
    }
#pragma unroll
    for (int o = 16; o; o >>= 1) len += __shfl_xor_sync(FULL, len, o);

    float Trow[K];
#pragma unroll
    for (int k = 0; k < K; ++k) Trow[k] = Tm[j * K + k];

    const float* Pb = P + (size_t)b * L * K;
    const int lm1 = len - 1;

    // named-register emission pipeline, depth 4
    float e0 = __ldg(Pb + 0 * K + j);
    float e1 = __ldg(Pb + min(1, lm1) * K + j);
    float e2 = __ldg(Pb + min(2, lm1) * K + j);
    float e3 = __ldg(Pb + min(3, lm1) * K + j);

    // init both DP buffers (index 19 is read as part of a float4 but unused)
    if (lane < 20) {
        dpbuf[wid][0][lane] = (lane == START_ID) ? 0.0f : NEG;
        dpbuf[wid][1][lane] = NEG;
    }
    __syncwarp();

    float nd = (j == START_ID && lane < K) ? 0.0f : NEG;
    unsigned int* bpw = (unsigned int*)bp + lane;     // + 20 per 4-step group

    int t = 0;
    // ---- main loop, 4 steps per iteration (buffer parity 0->1->0->1->0) ----
    for (; t + 4 <= len; t += 4) {
        int a0, a1, a2, a3;
        FSTEP(0, 1, e0, a0);  e0 = __ldg(Pb + min(t + 4, lm1) * K + j);
        FSTEP(1, 0, e1, a1);  e1 = __ldg(Pb + min(t + 5, lm1) * K + j);
        FSTEP(0, 1, e2, a2);  e2 = __ldg(Pb + min(t + 6, lm1) * K + j);
        FSTEP(1, 0, e3, a3);  e3 = __ldg(Pb + min(t + 7, lm1) * K + j);
        if (lane < K)
            *bpw = (unsigned)a0 | ((unsigned)a1 << 8) |
                   ((unsigned)a2 << 16) | ((unsigned)a3 << 24);
        bpw += 20;
    }
    // ---- tail (0..3 steps), starts at buffer 0 ----
    {
        const int r = len - t;
        if (r > 0) {
            int a0 = 0, a1 = 0, a2 = 0;
            FSTEP(0, 1, e0, a0);
            if (r > 1) FSTEP(1, 0, e1, a1);
            if (r > 2) FSTEP(0, 1, e2, a2);
            if (lane < K)
                *bpw = (unsigned)a0 | ((unsigned)a1 << 8) | ((unsigned)a2 << 16);
        }
    }

    // ---- final transition into PAD, first-occurrence argmax ----
    const float fv = (lane < K) ? (nd + Tm[PAD_ID * K + j]) : NEG;
    int last = 0;
    {
        float bestf = __shfl_sync(FULL, fv, 0);
#pragma unroll
        for (int k = 1; k < K; ++k) {
            const float vk = __shfl_sync(FULL, fv, k);
            if (vk > bestf) { bestf = vk; last = k; }
        }
    }

    float* ob = out + (size_t)b * L;
    for (int tt = len + lane; tt < L; tt += 32) ob[tt] = -1.0f;

    // ---- backtrack, warp-local two-pass ----
    const int segw = (len + NSEG - 1) / NSEG;
    const int nseg = (len + segw - 1) / segw;

    // pass 1: chain (segment i, end-state e) -> state at segment start
    int cur[CPL], tq[CPL], t0q[CPL];
#pragma unroll
    for (int q = 0; q < CPL; ++q) {
        const int cid = lane + 32 * q;
        if (cid < nseg * K) {
            const int i = cid / K, e = cid - i * K;
            const int t0 = i * segw;
            const int t1 = min(t0 + segw, len);
            cur[q] = e; tq[q] = t1 - 1; t0q[q] = t0;
        } else { cur[q] = 0; tq[q] = 0; t0q[q] = 0; }
    }
    for (int p = 0; p < segw - 1; ++p) {
#pragma unroll
        for (int q = 0; q < CPL; ++q)
            if (tq[q] > t0q[q]) {
                cur[q] = BPGET(bp, tq[q], cur[q]);
                tq[q]--;
            }
    }
#pragma unroll
    for (int q = 0; q < CPL; ++q) {
        const int cid = lane + 32 * q;
        if (cid < nseg * K) {
            const int i = cid / K, e = cid - i * K;
            fmap[wid][i][e] = (unsigned char)cur[q];
        }
    }
    __syncwarp();

    if (lane == 0) {
        int e = last;
        eseg[wid][nseg - 1] = (unsigned char)e;
        for (int i = nseg - 1; i > 0; --i) {
            const int t0 = i * segw;
            const int pc = fmap[wid][i][e];       // path[t0]
            e = BPGET(bp, t0, pc);                // path[t0-1]
            eseg[wid][i - 1] = (unsigned char)e;
        }
    }
    __syncwarp();

    // pass 2: each lane decodes one segment
    if (lane < nseg) {
        const int t0 = lane * segw;
        const int t1 = min(t0 + segw, len);
        int c = eseg[wid][lane];
        ob[t1 - 1] = (float)c;
        for (int tt = t1 - 2; tt >= t0; --tt) {
            c = BPGET(bp, tt + 1, c);
            ob[tt] = (float)c;
        }
    }
}

extern "C" void kernel_launch(void* const* d_in, const int* in_sizes, int n_in,
                              void* d_out, int out_size) {
    const float* P = (const float*)d_in[0];
    const float* T = (const float*)d_in[1];
    const unsigned char* mask = (const unsigned char*)d_in[2];
    float* out = (float*)d_out;

    const int smem = NW * ROWBYTES;  // 163840 B
    cudaFuncSetAttribute(viterbi_kernel,
                         cudaFuncAttributeMaxDynamicSharedMemorySize, smem);

    detect_kernel<<<1, 256>>>(mask);
    viterbi_kernel<<<B / NW, NW * 32, smem>>>(P, T, mask, out);
}

// round 9
// speedup vs baseline: 4.1319x; 1.1058x over previous
#include <cuda_runtime.h>

#define K 19
#define L 2048
#define B 512
#define START_ID 17
#define PAD_ID 18
#define NEG -1000.0f
#define NW 4            // rows (warps) per block
#define NSEG 16         // backtrack segments per row
#define CPL 10          // boundary chains per lane: ceil(16*19/32)
#define FULL 0xffffffffu
#define ROWBYTES (L / 8 * 160)  // packed bp: [L/8 groups][20 lanes][8 bytes]

__device__ int g_elt4;

__global__ void detect_kernel(const unsigned char* __restrict__ m) {
    __shared__ int found;
    if (threadIdx.x == 0) found = 0;
    __syncthreads();
    int f = 0;
    for (int i = threadIdx.x * 4 + 1; i < 65536; i += blockDim.x * 4)
        f |= m[i];
    if (f) found = 1;
    __syncthreads();
    if (threadIdx.x == 0) g_elt4 = found ? 0 : 1;
}

// bp(t, c) for packed layout: group t/8, 20 lanes x 8 bytes
__device__ __forceinline__ int BPGET(const unsigned char* bp, int t, int c) {
    return bp[((t >> 3) * 160) + (c << 3) + (t & 7)];
}

// chain link: strict '>' keeps FIRST occurrence (ascending k)
#define LNK(SS, kk, cc, ii)                                       \
    ii = (SS > cc) ? kk : ii;                                     \
    cc = fmaxf(cc, SS);

// one Viterbi step; chains aligned to float4 quads; one syncwarp.
#define FSTEP(CUR, NXT, EMIT, ARGOUT) do {                                 \
    float d[20];                                                           \
    *(float4*)&d[0]  = *(const float4*)&dpbuf[wid][CUR][0];                \
    *(float4*)&d[4]  = *(const float4*)&dpbuf[wid][CUR][4];                \
    *(float4*)&d[8]  = *(const float4*)&dpbuf[wid][CUR][8];                \
    *(float4*)&d[12] = *(const float4*)&dpbuf[wid][CUR][12];               \
    *(float4*)&d[16] = *(const float4*)&dpbuf[wid][CUR][16];               \
    float s[19];                                                           \
    s[0]=d[0]+Trow[0];   s[1]=d[1]+Trow[1];   s[2]=d[2]+Trow[2];           \
    s[3]=d[3]+Trow[3];   s[4]=d[4]+Trow[4];   s[5]=d[5]+Trow[5];           \
    s[6]=d[6]+Trow[6];   s[7]=d[7]+Trow[7];   s[8]=d[8]+Trow[8];           \
    s[9]=d[9]+Trow[9];   s[10]=d[10]+Trow[10];s[11]=d[11]+Trow[11];        \
    s[12]=d[12]+Trow[12];s[13]=d[13]+Trow[13];s[14]=d[14]+Trow[14];        \
    s[15]=d[15]+Trow[15];s[16]=d[16]+Trow[16];s[17]=d[17]+Trow[17];        \
    s[18]=d[18]+Trow[18];                                                  \
    float c0=s[0];  int i0=0;   LNK(s[1],1,c0,i0)   LNK(s[2],2,c0,i0)      \
    LNK(s[3],3,c0,i0)                                                      \
    float c1=s[4];  int i1=4;   LNK(s[5],5,c1,i1)   LNK(s[6],6,c1,i1)      \
    LNK(s[7],7,c1,i1)                                                      \
    float c2=s[8];  int i2=8;   LNK(s[9],9,c2,i2)   LNK(s[10],10,c2,i2)    \
    LNK(s[11],11,c2,i2)                                                    \
    float c3=s[12]; int i3=12;  LNK(s[13],13,c3,i3) LNK(s[14],14,c3,i3)    \
    LNK(s[15],15,c3,i3)                                                    \
    float c4=s[16]; int i4=16;  LNK(s[17],17,c4,i4) LNK(s[18],18,c4,i4)    \
    int   i01 = (c1 > c0) ? i1 : i0;   float m01 = fmaxf(c0, c1);          \
    int   i23 = (c3 > c2) ? i3 : i2;   float m23 = fmaxf(c2, c3);          \
    int   ia  = (m23 > m01) ? i23 : i01; float ma = fmaxf(m01, m23);       \
    ARGOUT = (c4 > ma) ? i4 : ia;                                          \
    nd = fmaxf(ma, c4) + (EMIT);                                           \
    dpbuf[wid][NXT][lane] = nd;                                            \
    __syncwarp();                                                          \
} while (0)

__global__ void __launch_bounds__(NW * 32, 1) viterbi_kernel(
    const float* __restrict__ P,          // [B, L, K]
    const float* __restrict__ Tm,         // [K, K]: T[j*K+k], prev k -> cur j
    const unsigned char* __restrict__ mask,
    float* __restrict__ out)              // [B, L] float32
{
    extern __shared__ unsigned char dsm[];            // NW * ROWBYTES
    __shared__ __align__(16) float dpbuf[NW][2][32];  // padded DP double buffer
    __shared__ unsigned char fmap[NW][NSEG][K];
    __shared__ unsigned char eseg[NW][NSEG];

    const int wid  = threadIdx.x >> 5;
    const int lane = threadIdx.x & 31;
    const int b    = blockIdx.x * NW + wid;
    const int j    = (lane < K) ? lane : 0;

    unsigned char* __restrict__ bp = dsm + wid * ROWBYTES;

    // ---- sequence length ----
    int len = 0;
    if (g_elt4) {
        const unsigned int* m = (const unsigned int*)mask + (size_t)b * L;
        for (int i = lane; i < L; i += 32) len += (m[i] != 0u);
    } else {
        const unsigned char* m = mask + (size_t)b * L;
        for (int i = lane; i < L; i += 32) len += (m[i] != 0);
    }
#pragma unroll
    for (int o = 16; o; o >>= 1) len += __shfl_xor_sync(FULL, len, o);

    float Trow[K];
#pragma unroll
    for (int k = 0; k < K; ++k) Trow[k] = Tm[j * K + k];

    const float* Pb = P + (size_t)b * L * K;
    const int lm1 = len - 1;

    // named-register emission pipeline, depth 8
    float e0 = __ldg(Pb + 0 * K + j);
    float e1 = __ldg(Pb + min(1, lm1) * K + j);
    float e2 = __ldg(Pb + min(2, lm1) * K + j);
    float e3 = __ldg(Pb + min(3, lm1) * K + j);
    float e4 = __ldg(Pb + min(4, lm1) * K + j);
    float e5 = __ldg(Pb + min(5, lm1) * K + j);
    float e6 = __ldg(Pb + min(6, lm1) * K + j);
    float e7 = __ldg(Pb + min(7, lm1) * K + j);

    // init both DP buffers (slots 19..31 padding, written but never read)
    dpbuf[wid][0][lane] = (lane == START_ID) ? 0.0f : NEG;
    dpbuf[wid][1][lane] = NEG;
    __syncwarp();

    float nd = (j == START_ID && lane < K) ? 0.0f : NEG;
    unsigned long long* bpq = (unsigned long long*)bp + lane; // +20 per group

    int t = 0;
    // ---- main loop, 8 steps per iteration ----
    for (; t + 8 <= len; t += 8) {
        int a0, a1, a2, a3, a4, a5, a6, a7;
        FSTEP(0, 1, e0, a0);  e0 = __ldg(Pb + min(t + 8, lm1) * K + j);
        FSTEP(1, 0, e1, a1);  e1 = __ldg(Pb + min(t + 9, lm1) * K + j);
        FSTEP(0, 1, e2, a2);  e2 = __ldg(Pb + min(t + 10, lm1) * K + j);
        FSTEP(1, 0, e3, a3);  e3 = __ldg(Pb + min(t + 11, lm1) * K + j);
        FSTEP(0, 1, e4, a4);  e4 = __ldg(Pb + min(t + 12, lm1) * K + j);
        FSTEP(1, 0, e5, a5);  e5 = __ldg(Pb + min(t + 13, lm1) * K + j);
        FSTEP(0, 1, e6, a6);  e6 = __ldg(Pb + min(t + 14, lm1) * K + j);
        FSTEP(1, 0, e7, a7);  e7 = __ldg(Pb + min(t + 15, lm1) * K + j);
        if (lane < K) {
            unsigned w0 = (unsigned)a0 | ((unsigned)a1 << 8) |
                          ((unsigned)a2 << 16) | ((unsigned)a3 << 24);
            unsigned w1 = (unsigned)a4 | ((unsigned)a5 << 8) |
                          ((unsigned)a6 << 16) | ((unsigned)a7 << 24);
            *bpq = (unsigned long long)w0 | ((unsigned long long)w1 << 32);
        }
        bpq += 20;
    }
    // ---- tail (0..7 steps), parity starts at 0 ----
    {
        const int r = len - t;
        if (r > 0) {
            int a0 = 0, a1 = 0, a2 = 0, a3 = 0, a4 = 0, a5 = 0, a6 = 0;
            FSTEP(0, 1, e0, a0);
            if (r > 1) FSTEP(1, 0, e1, a1);
            if (r > 2) FSTEP(0, 1, e2, a2);
            if (r > 3) FSTEP(1, 0, e3, a3);
            if (r > 4) FSTEP(0, 1, e4, a4);
            if (r > 5) FSTEP(1, 0, e5, a5);
            if (r > 6) FSTEP(0, 1, e6, a6);
            if (lane < K) {
                unsigned w0 = (unsigned)a0 | ((unsigned)a1 << 8) |
                              ((unsigned)a2 << 16) | ((unsigned)a3 << 24);
                unsigned w1 = (unsigned)a4 | ((unsigned)a5 << 8) |
                              ((unsigned)a6 << 16);
                *bpq = (unsigned long long)w0 | ((unsigned long long)w1 << 32);
            }
        }
    }

    // ---- final transition into PAD, first-occurrence argmax ----
    const float fv = (lane < K) ? (nd + Tm[PAD_ID * K + j]) : NEG;
    int last = 0;
    {
        float bestf = __shfl_sync(FULL, fv, 0);
#pragma unroll
        for (int k = 1; k < K; ++k) {
            const float vk = __shfl_sync(FULL, fv, k);
            if (vk > bestf) { bestf = vk; last = k; }
        }
    }

    float* ob = out + (size_t)b * L;
    for (int tt = len + lane; tt < L; tt += 32) ob[tt] = -1.0f;

    // ---- backtrack, warp-local two-pass ----
    const int segw = (len + NSEG - 1) / NSEG;
    const int nseg = (len + segw - 1) / segw;

    // pass 1: chain (segment i, end-state e) -> state at segment start
    int cur[CPL], tq[CPL], t0q[CPL];
#pragma unroll
    for (int q = 0; q < CPL; ++q) {
        const int cid = lane + 32 * q;
        if (cid < nseg * K) {
            const int i = cid / K, e = cid - i * K;
            const int t0 = i * segw;
            const int t1 = min(t0 + segw, len);
            cur[q] = e; tq[q] = t1 - 1; t0q[q] = t0;
        } else { cur[q] = 0; tq[q] = 0; t0q[q] = 0; }
    }
    for (int p = 0; p < segw - 1; ++p) {
#pragma unroll
        for (int q = 0; q < CPL; ++q)
            if (tq[q] > t0q[q]) {
                cur[q] = BPGET(bp, tq[q], cur[q]);
                tq[q]--;
            }
    }
#pragma unroll
    for (int q = 0; q < CPL; ++q) {
        const int cid = lane + 32 * q;
        if (cid < nseg * K) {
            const int i = cid / K, e = cid - i * K;
            fmap[wid][i][e] = (unsigned char)cur[q];
        }
    }
    __syncwarp();

    if (lane == 0) {
        int e = last;
        eseg[wid][nseg - 1] = (unsigned char)e;
        for (int i = nseg - 1; i > 0; --i) {
            const int t0 = i * segw;
            const int pc = fmap[wid][i][e];       // path[t0]
            e = BPGET(bp, t0, pc);                // path[t0-1]
            eseg[wid][i - 1] = (unsigned char)e;
        }
    }
    __syncwarp();

    // pass 2: each lane decodes one segment
    if (lane < nseg) {
        const int t0 = lane * segw;
        const int t1 = min(t0 + segw, len);
        int c = eseg[wid][lane];
        ob[t1 - 1] = (float)c;
        for (int tt = t1 - 2; tt >= t0; --tt) {
            c = BPGET(bp, tt + 1, c);
            ob[tt] = (float)c;
        }
    }
}

extern "C" void kernel_launch(void* const* d_in, const int* in_sizes, int n_in,
                              void* d_out, int out_size) {
    const float* P = (const float*)d_in[0];
    const float* T = (const float*)d_in[1];
    const unsigned char* mask = (const unsigned char*)d_in[2];
    float* out = (float*)d_out;

    const int smem = NW * ROWBYTES;  // 163840 B
    cudaFuncSetAttribute(viterbi_kernel,
                         cudaFuncAttributeMaxDynamicSharedMemorySize, smem);

    detect_kernel<<<1, 256>>>(mask);
    viterbi_kernel<<<B / NW, NW * 32, smem>>>(P, T, mask, out);
}